// round 1
// baseline (speedup 1.0000x reference)
#include <cuda_runtime.h>

#define B_    16
#define C_    64
#define COUT_ 64
#define L_    16384
#define K_    3
#define CK_   (K_ * C_)   // 192
#define TL_   64          // l-positions per block

// ---------------- scratch (no allocations allowed) ----------------
__device__ float g_off[B_ * L_ * K_];   // [b][l][k]
__device__ float g_msk[B_ * L_ * K_];   // [b][l][k]
__device__ float g_wt[CK_ * COUT_];     // [ck][o], ck = k*64 + c

// ---------------- f32x2 helpers ----------------
__device__ __forceinline__ unsigned long long pack2(float lo, float hi) {
    unsigned long long r;
    asm("mov.b64 %0, {%1, %2};" : "=l"(r) : "f"(lo), "f"(hi));
    return r;
}
__device__ __forceinline__ void unpack2(unsigned long long v, float& lo, float& hi) {
    asm("mov.b64 {%0, %1}, %2;" : "=f"(lo), "=f"(hi) : "l"(v));
}
__device__ __forceinline__ void fma2(unsigned long long& d, unsigned long long a,
                                     unsigned long long b) {
    asm("fma.rn.f32x2 %0, %1, %2, %0;" : "+l"(d) : "l"(a), "l"(b));
}

// ================= kernel A: weight transpose =================
// weight[o][c][k] -> g_wt[(k*64+c)*64 + o]
__global__ void wt_kernel(const float* __restrict__ weight) {
    int i = blockIdx.x * blockDim.x + threadIdx.x;
    if (i < CK_ * COUT_) {
        int o  = i & 63;
        int ck = i >> 6;
        int c  = ck & 63;
        int k  = ck >> 6;
        g_wt[i] = weight[o * CK_ + c * K_ + k];
    }
}

// ================= kernel B: offset / mask branches =================
// per (b,l): depthwise k=7 conv (pad 3) over 64 channels, then 1x1 -> 3 ch
__global__ __launch_bounds__(256) void offmsk_kernel(
    const float* __restrict__ x,
    const float* __restrict__ wodw, const float* __restrict__ bodw,
    const float* __restrict__ wopw, const float* __restrict__ bopw,
    const float* __restrict__ wmdw, const float* __restrict__ bmdw,
    const float* __restrict__ wmpw, const float* __restrict__ bmpw)
{
    __shared__ float s_wdwA[64 * 7], s_wdwB[64 * 7];
    __shared__ float s_bdwA[64],     s_bdwB[64];
    __shared__ float s_wpwA[3 * 64], s_wpwB[3 * 64];
    __shared__ float s_bpwA[4],      s_bpwB[4];
    __shared__ float s_dwA[64 * 65], s_dwB[64 * 65];   // [l][c], padded

    const int tid = threadIdx.x;
    const int b   = blockIdx.y;
    const int l0  = blockIdx.x * TL_;

    for (int i = tid; i < 448; i += 256) { s_wdwA[i] = wodw[i]; s_wdwB[i] = wmdw[i]; }
    if (tid < 64)  { s_bdwA[tid] = bodw[tid]; s_bdwB[tid] = bmdw[tid]; }
    for (int i = tid; i < 192; i += 256) { s_wpwA[i] = wopw[i]; s_wpwB[i] = wmpw[i]; }
    if (tid < 3)   { s_bpwA[tid] = bopw[tid]; s_bpwB[tid] = bmpw[tid]; }
    __syncthreads();

    // phase 1: depthwise 7-tap conv for both branches, items = (li, c)
    #pragma unroll
    for (int it = 0; it < 16; ++it) {
        int item = it * 256 + tid;
        int li = item & 63;          // lanes consecutive in l -> coalesced x reads
        int c  = item >> 6;
        const float* xr = x + (long)(b * 64 + c) * L_;
        float sA = s_bdwA[c], sB = s_bdwB[c];
        #pragma unroll
        for (int t = 0; t < 7; ++t) {
            int idx = l0 + li - 3 + t;
            float xv = (idx >= 0 && idx < L_) ? xr[idx] : 0.f;
            sA = fmaf(xv, s_wdwA[c * 7 + t], sA);
            sB = fmaf(xv, s_wdwB[c * 7 + t], sB);
        }
        s_dwA[li * 65 + c] = sA;
        s_dwB[li * 65 + c] = sB;
    }
    __syncthreads();

    // phase 2: 1x1 conv over c -> 3 outputs, sigmoid for mask branch
    if (tid < 192) {
        int li = tid / 3;
        int k  = tid - li * 3;
        float oA = s_bpwA[k], oB = s_bpwB[k];
        #pragma unroll 8
        for (int c = 0; c < 64; ++c) {
            oA = fmaf(s_dwA[li * 65 + c], s_wpwA[k * 64 + c], oA);
            oB = fmaf(s_dwB[li * 65 + c], s_wpwB[k * 64 + c], oB);
        }
        long gi = ((long)(b * L_ + l0 + li)) * 3 + k;
        g_off[gi] = oA;
        g_msk[gi] = 1.f / (1.f + expf(-oB));
    }
}

// ================= kernel C: gather + interp + contraction =================
// dynamic smem: w_s[192*64] (48KB) | xv_s[64*192] (48KB); out staging reuses w_s
__global__ __launch_bounds__(256, 2) void main_kernel(
    const float* __restrict__ x,
    const float* __restrict__ bias,
    float* __restrict__ out)
{
    extern __shared__ float smem[];
    float* w_s  = smem;          // [ck][o]
    float* xv_s = smem + CK_ * COUT_;  // [li][ck]

    __shared__ float off_s[192], msk_s[192], bias_s[64];

    const int tid = threadIdx.x;
    const int b   = blockIdx.y;
    const int l0  = blockIdx.x * TL_;

    for (int i = tid; i < CK_ * COUT_; i += 256) w_s[i] = g_wt[i];
    if (tid < 192) {
        long gi = (long)(b * L_ + l0) * 3 + tid;
        off_s[tid] = g_off[gi];
        msk_s[tid] = g_msk[gi];
    }
    if (tid < 64) bias_s[tid] = bias[tid];
    __syncthreads();

    // ---- phase A: build xv[li][k*64+c] = interp(x) * mask ----
    {
        int c  = tid & 63;   // lanes over c -> contiguous smem writes
        int s0 = tid >> 6;   // 4 slices in flight
        const float* xr = x + (long)(b * 64 + c) * L_;
        #pragma unroll 4
        for (int it = 0; it < 48; ++it) {
            int slice = it * 4 + s0;       // 0..191
            int li = slice / 3;
            int k  = slice - li * 3;
            float off = off_s[li * 3 + k];
            float m   = msk_s[li * 3 + k];
            float p  = (float)(l0 + li - 1 + k) + off;
            float fi = floorf(p);
            float f  = p - fi;
            int i0 = (int)fi;
            int i1 = i0 + 1;
            float x0 = (i0 >= 0 && i0 < L_) ? xr[i0] : 0.f;
            float x1 = (i1 >= 0 && i1 < L_) ? xr[i1] : 0.f;
            xv_s[li * CK_ + k * 64 + c] = ((1.f - f) * x0 + f * x1) * m;
        }
    }
    __syncthreads();

    // ---- phase B: out[o, l] = sum_ck w[ck][o] * xv[l][ck] ----
    // thread owns 4 o (2 f32x2 pairs) x 4 l
    const int og = tid & 15;
    const int lg = tid >> 4;
    const int obase = og * 4;
    const int lbase = lg * 4;

    unsigned long long acc[8];
    #pragma unroll
    for (int i = 0; i < 8; ++i) acc[i] = 0ULL;

    const float* xvp = xv_s + lbase * CK_;

    #pragma unroll 2
    for (int s = 0; s < 48; ++s) {
        int ck0 = s * 4;
        float4 xa = *(const float4*)(xvp + 0 * CK_ + ck0);
        float4 xb = *(const float4*)(xvp + 1 * CK_ + ck0);
        float4 xc = *(const float4*)(xvp + 2 * CK_ + ck0);
        float4 xd = *(const float4*)(xvp + 3 * CK_ + ck0);
        const float* xaf = (const float*)&xa;
        const float* xbf = (const float*)&xb;
        const float* xcf = (const float*)&xc;
        const float* xdf = (const float*)&xd;
        #pragma unroll
        for (int kk = 0; kk < 4; ++kk) {
            const float* wr = w_s + (ck0 + kk) * 64 + obase;
            unsigned long long wp0 = *(const unsigned long long*)(wr);      // o, o+1
            unsigned long long wp1 = *(const unsigned long long*)(wr + 2);  // o+2, o+3
            float xs0 = xaf[kk], xs1 = xbf[kk], xs2 = xcf[kk], xs3 = xdf[kk];
            unsigned long long d0 = pack2(xs0, xs0);
            unsigned long long d1 = pack2(xs1, xs1);
            unsigned long long d2 = pack2(xs2, xs2);
            unsigned long long d3 = pack2(xs3, xs3);
            fma2(acc[0], wp0, d0); fma2(acc[4], wp1, d0);
            fma2(acc[1], wp0, d1); fma2(acc[5], wp1, d1);
            fma2(acc[2], wp0, d2); fma2(acc[6], wp1, d2);
            fma2(acc[3], wp0, d3); fma2(acc[7], wp1, d3);
        }
    }
    __syncthreads();

    // ---- stage output in smem (reuse w_s) for coalesced stores ----
    float* out_s = smem;   // [o][l] padded to 65
    #pragma unroll
    for (int op = 0; op < 2; ++op) {
        #pragma unroll
        for (int j = 0; j < 4; ++j) {
            float lo, hi;
            unpack2(acc[op * 4 + j], lo, hi);
            out_s[(obase + op * 2 + 0) * 65 + lbase + j] = lo;
            out_s[(obase + op * 2 + 1) * 65 + lbase + j] = hi;
        }
    }
    __syncthreads();

    for (int i = tid; i < 64 * 64; i += 256) {
        int o = i >> 6;
        int l = i & 63;
        out[((long)(b * 64 + o)) * L_ + l0 + l] = out_s[o * 65 + l] + bias_s[o];
    }
}

// ================= host =================
extern "C" void kernel_launch(void* const* d_in, const int* in_sizes, int n_in,
                              void* d_out, int out_size) {
    const float* x      = (const float*)d_in[0];
    const float* wodw   = (const float*)d_in[1];
    const float* bodw   = (const float*)d_in[2];
    const float* wopw   = (const float*)d_in[3];
    const float* bopw   = (const float*)d_in[4];
    const float* wmdw   = (const float*)d_in[5];
    const float* bmdw   = (const float*)d_in[6];
    const float* wmpw   = (const float*)d_in[7];
    const float* bmpw   = (const float*)d_in[8];
    const float* weight = (const float*)d_in[9];
    const float* bias   = (const float*)d_in[10];
    float* out = (float*)d_out;

    wt_kernel<<<(CK_ * COUT_ + 255) / 256, 256>>>(weight);

    dim3 grid(L_ / TL_, B_);
    offmsk_kernel<<<grid, 256>>>(x, wodw, bodw, wopw, bopw,
                                 wmdw, bmdw, wmpw, bmpw);

    const int smem_c = (CK_ * COUT_ + TL_ * CK_) * (int)sizeof(float);  // 98304
    cudaFuncSetAttribute(main_kernel, cudaFuncAttributeMaxDynamicSharedMemorySize, smem_c);
    main_kernel<<<grid, 256, smem_c>>>(x, bias, out);
}

// round 2
// speedup vs baseline: 1.0073x; 1.0073x over previous
#include <cuda_runtime.h>

#define B_    16
#define C_    64
#define COUT_ 64
#define L_    16384
#define K_    3
#define CK_   (K_ * C_)   // 192
#define TL_   64          // l-positions per block

// ---------------- scratch (no allocations allowed) ----------------
__device__ float g_off[B_ * L_ * K_];   // [b][l][k]
__device__ float g_msk[B_ * L_ * K_];   // [b][l][k]
__device__ float g_wt[CK_ * COUT_];     // [ck][o], ck = k*64 + c

// ---------------- f32x2 helpers ----------------
__device__ __forceinline__ unsigned long long pack2(float lo, float hi) {
    unsigned long long r;
    asm("mov.b64 %0, {%1, %2};" : "=l"(r) : "f"(lo), "f"(hi));
    return r;
}
__device__ __forceinline__ void unpack2(unsigned long long v, float& lo, float& hi) {
    asm("mov.b64 {%0, %1}, %2;" : "=f"(lo), "=f"(hi) : "l"(v));
}
__device__ __forceinline__ void fma2(unsigned long long& d, unsigned long long a,
                                     unsigned long long b) {
    asm("fma.rn.f32x2 %0, %1, %2, %0;" : "+l"(d) : "l"(a), "l"(b));
}

// ================= kernel A: weight transpose =================
__global__ void wt_kernel(const float* __restrict__ weight) {
    int i = blockIdx.x * blockDim.x + threadIdx.x;
    if (i < CK_ * COUT_) {
        int o  = i & 63;
        int ck = i >> 6;
        int c  = ck & 63;
        int k  = ck >> 6;
        g_wt[i] = weight[o * CK_ + c * K_ + k];
    }
}

// ================= kernel B: offset / mask branches =================
__global__ __launch_bounds__(256) void offmsk_kernel(
    const float* __restrict__ x,
    const float* __restrict__ wodw, const float* __restrict__ bodw,
    const float* __restrict__ wopw, const float* __restrict__ bopw,
    const float* __restrict__ wmdw, const float* __restrict__ bmdw,
    const float* __restrict__ wmpw, const float* __restrict__ bmpw)
{
    __shared__ float s_wdwA[64 * 7], s_wdwB[64 * 7];
    __shared__ float s_bdwA[64],     s_bdwB[64];
    __shared__ float s_wpwA[3 * 64], s_wpwB[3 * 64];
    __shared__ float s_bpwA[4],      s_bpwB[4];
    __shared__ float s_dwA[64 * 65], s_dwB[64 * 65];   // [l][c], padded

    const int tid = threadIdx.x;
    const int b   = blockIdx.y;
    const int l0  = blockIdx.x * TL_;

    for (int i = tid; i < 448; i += 256) { s_wdwA[i] = wodw[i]; s_wdwB[i] = wmdw[i]; }
    if (tid < 64)  { s_bdwA[tid] = bodw[tid]; s_bdwB[tid] = bmdw[tid]; }
    for (int i = tid; i < 192; i += 256) { s_wpwA[i] = wopw[i]; s_wpwB[i] = wmpw[i]; }
    if (tid < 3)   { s_bpwA[tid] = bopw[tid]; s_bpwB[tid] = bmpw[tid]; }
    __syncthreads();

    #pragma unroll
    for (int it = 0; it < 16; ++it) {
        int item = it * 256 + tid;
        int li = item & 63;          // lanes consecutive in l -> coalesced x reads
        int c  = item >> 6;
        const float* xr = x + (long)(b * 64 + c) * L_;
        float sA = s_bdwA[c], sB = s_bdwB[c];
        #pragma unroll
        for (int t = 0; t < 7; ++t) {
            int idx = l0 + li - 3 + t;
            float xv = (idx >= 0 && idx < L_) ? xr[idx] : 0.f;
            sA = fmaf(xv, s_wdwA[c * 7 + t], sA);
            sB = fmaf(xv, s_wdwB[c * 7 + t], sB);
        }
        s_dwA[li * 65 + c] = sA;
        s_dwB[li * 65 + c] = sB;
    }
    __syncthreads();

    if (tid < 192) {
        int li = tid / 3;
        int k  = tid - li * 3;
        float oA = s_bpwA[k], oB = s_bpwB[k];
        #pragma unroll 8
        for (int c = 0; c < 64; ++c) {
            oA = fmaf(s_dwA[li * 65 + c], s_wpwA[k * 64 + c], oA);
            oB = fmaf(s_dwB[li * 65 + c], s_wpwB[k * 64 + c], oB);
        }
        long gi = ((long)(b * L_ + l0 + li)) * 3 + k;
        g_off[gi] = oA;
        g_msk[gi] = 1.f / (1.f + expf(-oB));
    }
}

// ================= kernel C: gather + interp + contraction =================
// dynamic smem: w_s[ck][o] 48KB | xv_s[ck][li] 48KB (TRANSPOSED vs round 1)
// 128 threads, 2 blocks/SM
__global__ __launch_bounds__(128, 2) void main_kernel(
    const float* __restrict__ x,
    const float* __restrict__ bias,
    float* __restrict__ out)
{
    extern __shared__ float smem[];
    float* w_s  = smem;                 // [ck][o]   12288 floats
    float* xv_s = smem + CK_ * COUT_;   // [ck][li]  12288 floats

    __shared__ float off_s[192], msk_s[192], bias_s[64];

    const int tid = threadIdx.x;
    const int b   = blockIdx.y;
    const int l0  = blockIdx.x * TL_;

    // load weights (vectorized) + offsets/masks + bias
    {
        const float4* src = (const float4*)g_wt;
        float4* dst = (float4*)w_s;
        #pragma unroll
        for (int i = 0; i < 24; ++i) dst[i * 128 + tid] = src[i * 128 + tid];
    }
    for (int i = tid; i < 192; i += 128) {
        long gi = (long)(b * L_ + l0) * 3 + i;
        off_s[i] = g_off[gi];
        msk_s[i] = g_msk[gi];
    }
    if (tid < 64) bias_s[tid] = bias[tid];
    __syncthreads();

    // ---- phase A: xv_s[ck][li] = interp(x) * mask ; lanes over li (coalesced) ----
    #pragma unroll 4
    for (int it = 0; it < 96; ++it) {
        int idx = it * 128 + tid;
        int li = idx & 63;        // consecutive lanes -> consecutive gather positions
        int ck = idx >> 6;
        int c  = ck & 63;
        int k  = ck >> 6;
        float off = off_s[li * 3 + k];
        float m   = msk_s[li * 3 + k];
        const float* xr = x + (long)(b * 64 + c) * L_;
        float p  = (float)(l0 + li - 1 + k) + off;
        float fi = floorf(p);
        float f  = p - fi;
        int i0 = (int)fi;
        int i1 = i0 + 1;
        float x0 = (i0 >= 0 && i0 < L_) ? xr[i0] : 0.f;
        float x1 = (i1 >= 0 && i1 < L_) ? xr[i1] : 0.f;
        xv_s[ck * 64 + li] = ((1.f - f) * x0 + f * x1) * m;
    }
    __syncthreads();

    // ---- phase B: out[o][l] = sum_ck w[ck][o] * xv[ck][l] ----
    // thread owns 4 o x 8 l (4 l-pairs as f32x2); acc[oo*4 + lp]
    const int og = tid & 15;
    const int lg = tid >> 4;          // 0..7
    const int obase = og * 4;
    const int lbase = lg * 8;

    unsigned long long acc[16];
    #pragma unroll
    for (int i = 0; i < 16; ++i) acc[i] = 0ULL;

    #pragma unroll 2
    for (int ck = 0; ck < CK_; ++ck) {
        float4 wv = *(const float4*)(w_s + ck * 64 + obase);
        const unsigned long long* xp =
            (const unsigned long long*)(xv_s + ck * 64 + lbase);
        unsigned long long x01 = xp[0];
        unsigned long long x23 = xp[1];
        unsigned long long x45 = xp[2];
        unsigned long long x67 = xp[3];
        unsigned long long w0 = pack2(wv.x, wv.x);
        unsigned long long w1 = pack2(wv.y, wv.y);
        unsigned long long w2 = pack2(wv.z, wv.z);
        unsigned long long w3 = pack2(wv.w, wv.w);
        fma2(acc[0],  w0, x01); fma2(acc[1],  w0, x23);
        fma2(acc[2],  w0, x45); fma2(acc[3],  w0, x67);
        fma2(acc[4],  w1, x01); fma2(acc[5],  w1, x23);
        fma2(acc[6],  w1, x45); fma2(acc[7],  w1, x67);
        fma2(acc[8],  w2, x01); fma2(acc[9],  w2, x23);
        fma2(acc[10], w2, x45); fma2(acc[11], w2, x67);
        fma2(acc[12], w3, x01); fma2(acc[13], w3, x23);
        fma2(acc[14], w3, x45); fma2(acc[15], w3, x67);
    }
    __syncthreads();

    // ---- stage output (reuse w_s region) for coalesced stores ----
    float* out_s = smem;   // [o][l] stride 66
    #pragma unroll
    for (int oo = 0; oo < 4; ++oo) {
        #pragma unroll
        for (int jp = 0; jp < 4; ++jp) {
            float lo, hi;
            unpack2(acc[oo * 4 + jp], lo, hi);
            *(float2*)&out_s[(obase + oo) * 66 + lbase + jp * 2] =
                make_float2(lo, hi);
        }
    }
    __syncthreads();

    #pragma unroll
    for (int it = 0; it < 32; ++it) {
        int i = it * 128 + tid;
        int o = i >> 6;
        int l = i & 63;
        out[((long)(b * 64 + o)) * L_ + l0 + l] = out_s[o * 66 + l] + bias_s[o];
    }
}

// ================= host =================
extern "C" void kernel_launch(void* const* d_in, const int* in_sizes, int n_in,
                              void* d_out, int out_size) {
    const float* x      = (const float*)d_in[0];
    const float* wodw   = (const float*)d_in[1];
    const float* bodw   = (const float*)d_in[2];
    const float* wopw   = (const float*)d_in[3];
    const float* bopw   = (const float*)d_in[4];
    const float* wmdw   = (const float*)d_in[5];
    const float* bmdw   = (const float*)d_in[6];
    const float* wmpw   = (const float*)d_in[7];
    const float* bmpw   = (const float*)d_in[8];
    const float* weight = (const float*)d_in[9];
    const float* bias   = (const float*)d_in[10];
    float* out = (float*)d_out;

    wt_kernel<<<(CK_ * COUT_ + 255) / 256, 256>>>(weight);

    dim3 grid(L_ / TL_, B_);
    offmsk_kernel<<<grid, 256>>>(x, wodw, bodw, wopw, bopw,
                                 wmdw, bmdw, wmpw, bmpw);

    const int smem_c = 2 * CK_ * COUT_ * (int)sizeof(float);  // 98304
    cudaFuncSetAttribute(main_kernel, cudaFuncAttributeMaxDynamicSharedMemorySize, smem_c);
    main_kernel<<<grid, 128, smem_c>>>(x, bias, out);
}

// round 4
// speedup vs baseline: 1.3391x; 1.3295x over previous
#include <cuda_runtime.h>

#define B_    16
#define C_    64
#define COUT_ 64
#define L_    16384
#define K_    3
#define CK_   (K_ * C_)   // 192
#define TLC_  128         // l-positions per block (fused kernel)
#define XS_   137         // x window stride: TLC_ + 9 (covers dw taps + gather +-)
#define XWIN_ 137
#define OSTR_ 130         // output staging stride (even -> float2-aligned)

// scratch (no allocations allowed)
__device__ float g_wt[CK_ * COUT_];     // [ck][o], ck = k*64 + c

// ---------------- f32x2 helpers ----------------
__device__ __forceinline__ unsigned long long pack2(float lo, float hi) {
    unsigned long long r;
    asm("mov.b64 %0, {%1, %2};" : "=l"(r) : "f"(lo), "f"(hi));
    return r;
}
__device__ __forceinline__ void unpack2(unsigned long long v, float& lo, float& hi) {
    asm("mov.b64 {%0, %1}, %2;" : "=f"(lo), "=f"(hi) : "l"(v));
}
__device__ __forceinline__ void fma2(unsigned long long& d, unsigned long long a,
                                     unsigned long long b) {
    asm("fma.rn.f32x2 %0, %1, %2, %0;" : "+l"(d) : "l"(a), "l"(b));
}

// ================= kernel A: weight transpose =================
__global__ void wt_kernel(const float* __restrict__ weight) {
    int i = blockIdx.x * blockDim.x + threadIdx.x;
    if (i < CK_ * COUT_) {
        int o  = i & 63;
        int ck = i >> 6;
        int c  = ck & 63;
        int k  = ck >> 6;
        g_wt[i] = weight[o * CK_ + c * K_ + k];
    }
}

// ================= fused kernel =================
// dynamic smem layout (floats), total 45632 (182528 B):
//   x_s  [0, 8768)        64 ch x 137 window
//   w_s  [8768, 21056)    [ck][o]
//   dwA  [21056, 29376)   [li][c] stride 65   (dead after stage 2)
//   dwB  [29376, 37696)
//   xv_s [21056, 45632)   [ck][li]            (written after dw dead)
//   out_s reuses [0, 8320) stride 130 after phase B
__global__ __launch_bounds__(256, 1) void fused_kernel(
    const float* __restrict__ x,
    const float* __restrict__ wodw, const float* __restrict__ bodw,
    const float* __restrict__ wopw, const float* __restrict__ bopw,
    const float* __restrict__ wmdw, const float* __restrict__ bmdw,
    const float* __restrict__ wmpw, const float* __restrict__ bmpw,
    const float* __restrict__ bias,
    float* __restrict__ out)
{
    extern __shared__ float smem[];
    float* x_s  = smem;
    float* w_s  = smem + 8768;
    float* dwA  = smem + 21056;
    float* dwB  = smem + 29376;
    float* xv_s = smem + 21056;

    __shared__ float s_wdwA[448], s_wdwB[448];
    __shared__ float s_bdwA[64],  s_bdwB[64];
    __shared__ float s_wpwA[192], s_wpwB[192];
    __shared__ float s_bpwA[4],   s_bpwB[4];
    __shared__ float off_s[384], msk_s[384], bias_s[64];

    const int tid = threadIdx.x;
    const int b   = blockIdx.y;
    const int l0  = blockIdx.x * TLC_;

    // ---- stage 0: params + weights + x window ----
    for (int i = tid; i < 448; i += 256) { s_wdwA[i] = wodw[i]; s_wdwB[i] = wmdw[i]; }
    if (tid < 64)  { s_bdwA[tid] = bodw[tid]; s_bdwB[tid] = bmdw[tid]; bias_s[tid] = bias[tid]; }
    if (tid < 192) { s_wpwA[tid] = wopw[tid]; s_wpwB[tid] = wmpw[tid]; }
    if (tid < 3)   { s_bpwA[tid] = bopw[tid]; s_bpwB[tid] = bmpw[tid]; }

    {   // transposed conv weights (coalesced float4 from g_wt)
        const float4* src = (const float4*)g_wt;
        float4* dst = (float4*)w_s;
        #pragma unroll
        for (int i = 0; i < 12; ++i) dst[i * 256 + tid] = src[i * 256 + tid];
    }
    // x window: x_s[c*137 + lw] = x[b, c, l0-3+lw] (zero outside)
    #pragma unroll 4
    for (int i = tid; i < 64 * XS_; i += 256) {
        int c  = i / XS_;
        int lw = i - c * XS_;
        int idx = l0 - 3 + lw;
        x_s[i] = (idx >= 0 && idx < L_) ? x[(long)(b * 64 + c) * L_ + idx] : 0.f;
    }
    __syncthreads();

    // ---- stage 1: depthwise 7-tap conv, both branches ----
    #pragma unroll
    for (int it = 0; it < 32; ++it) {
        int item = it * 256 + tid;
        int li = item & 127;          // lanes consecutive in l
        int c  = item >> 7;
        const float* xr = x_s + c * XS_;   // x_s index for pos (l0+li-3+t) is li+t
        float sA = s_bdwA[c], sB = s_bdwB[c];
        #pragma unroll
        for (int t = 0; t < 7; ++t) {
            float xv = xr[li + t];
            sA = fmaf(xv, s_wdwA[c * 7 + t], sA);
            sB = fmaf(xv, s_wdwB[c * 7 + t], sB);
        }
        dwA[li * 65 + c] = sA;
        dwB[li * 65 + c] = sB;
    }
    __syncthreads();

    // ---- stage 2: 1x1 conv -> offset / mask (sigmoid) ----
    #pragma unroll
    for (int rep = 0; rep < 2; ++rep) {
        int item = rep * 256 + tid;
        if (item < 384) {
            int li = item / 3;
            int k  = item - li * 3;
            float oA = s_bpwA[k], oB = s_bpwB[k];
            #pragma unroll 8
            for (int c = 0; c < 64; ++c) {
                oA = fmaf(dwA[li * 65 + c], s_wpwA[k * 64 + c], oA);
                oB = fmaf(dwB[li * 65 + c], s_wpwB[k * 64 + c], oB);
            }
            off_s[item] = oA;
            msk_s[item] = 1.f / (1.f + expf(-oB));
        }
    }
    __syncthreads();

    // ---- stage 3: deformable gather + interp -> xv_s[ck][li] ----
    #pragma unroll 4
    for (int it = 0; it < 96; ++it) {
        int idx = it * 256 + tid;
        int li = idx & 127;           // lanes consecutive in l
        int ck = idx >> 7;
        int c  = ck & 63;
        int k  = ck >> 6;
        float off = off_s[li * 3 + k];
        float m   = msk_s[li * 3 + k];
        float p  = (float)(l0 + li - 1 + k) + off;
        float fi = floorf(p);
        float f  = p - fi;
        int i0 = (int)fi;
        int i1 = i0 + 1;
        int lw0 = i0 - (l0 - 3);
        int lw1 = lw0 + 1;
        const float* xr = x + (long)(b * 64 + c) * L_;
        float x0, x1;
        if (lw0 >= 0 && lw0 < XWIN_) x0 = x_s[c * XS_ + lw0];
        else x0 = (i0 >= 0 && i0 < L_) ? xr[i0] : 0.f;
        if (lw1 >= 0 && lw1 < XWIN_) x1 = x_s[c * XS_ + lw1];
        else x1 = (i1 >= 0 && i1 < L_) ? xr[i1] : 0.f;
        xv_s[ck * 128 + li] = ((1.f - f) * x0 + f * x1) * m;
    }
    __syncthreads();

    // ---- stage 4: out[o][l] = sum_ck w[ck][o] * xv[ck][l] ----
    // 4 o x 8 l per thread, f32x2 over l-pairs
    const int og = tid & 15;
    const int lg = tid >> 4;           // 0..15
    const int obase = og * 4;
    const int lbase = lg * 8;

    unsigned long long acc[16];
    #pragma unroll
    for (int i = 0; i < 16; ++i) acc[i] = 0ULL;

    #pragma unroll 2
    for (int ck = 0; ck < CK_; ++ck) {
        float4 wv = *(const float4*)(w_s + ck * 64 + obase);
        const unsigned long long* xp =
            (const unsigned long long*)(xv_s + ck * 128 + lbase);
        unsigned long long x01 = xp[0];
        unsigned long long x23 = xp[1];
        unsigned long long x45 = xp[2];
        unsigned long long x67 = xp[3];
        unsigned long long w0 = pack2(wv.x, wv.x);
        unsigned long long w1 = pack2(wv.y, wv.y);
        unsigned long long w2 = pack2(wv.z, wv.z);
        unsigned long long w3 = pack2(wv.w, wv.w);
        fma2(acc[0],  w0, x01); fma2(acc[1],  w0, x23);
        fma2(acc[2],  w0, x45); fma2(acc[3],  w0, x67);
        fma2(acc[4],  w1, x01); fma2(acc[5],  w1, x23);
        fma2(acc[6],  w1, x45); fma2(acc[7],  w1, x67);
        fma2(acc[8],  w2, x01); fma2(acc[9],  w2, x23);
        fma2(acc[10], w2, x45); fma2(acc[11], w2, x67);
        fma2(acc[12], w3, x01); fma2(acc[13], w3, x23);
        fma2(acc[14], w3, x45); fma2(acc[15], w3, x67);
    }
    __syncthreads();

    // ---- stage 5: stage + coalesced store (stride 130, float2-aligned) ----
    float* out_s = smem;   // [o][l] stride OSTR_
    #pragma unroll
    for (int oo = 0; oo < 4; ++oo) {
        #pragma unroll
        for (int jp = 0; jp < 4; ++jp) {
            float lo, hi;
            unpack2(acc[oo * 4 + jp], lo, hi);
            *(float2*)&out_s[(obase + oo) * OSTR_ + lbase + jp * 2] =
                make_float2(lo, hi);
        }
    }
    __syncthreads();

    #pragma unroll
    for (int it = 0; it < 32; ++it) {
        int i = it * 256 + tid;
        int o = i >> 7;
        int l = i & 127;
        out[((long)(b * 64 + o)) * L_ + l0 + l] = out_s[o * OSTR_ + l] + bias_s[o];
    }
}

// ================= host =================
extern "C" void kernel_launch(void* const* d_in, const int* in_sizes, int n_in,
                              void* d_out, int out_size) {
    const float* x      = (const float*)d_in[0];
    const float* wodw   = (const float*)d_in[1];
    const float* bodw   = (const float*)d_in[2];
    const float* wopw   = (const float*)d_in[3];
    const float* bopw   = (const float*)d_in[4];
    const float* wmdw   = (const float*)d_in[5];
    const float* bmdw   = (const float*)d_in[6];
    const float* wmpw   = (const float*)d_in[7];
    const float* bmpw   = (const float*)d_in[8];
    const float* weight = (const float*)d_in[9];
    const float* bias   = (const float*)d_in[10];
    float* out = (float*)d_out;

    wt_kernel<<<(CK_ * COUT_ + 255) / 256, 256>>>(weight);

    const int smem_f = 45632 * (int)sizeof(float);  // 182528 B
    cudaFuncSetAttribute(fused_kernel, cudaFuncAttributeMaxDynamicSharedMemorySize, smem_f);
    dim3 grid(L_ / TLC_, B_);
    fused_kernel<<<grid, 256, smem_f>>>(x, wodw, bodw, wopw, bopw,
                                        wmdw, bmdw, wmpw, bmpw, bias, out);
}

// round 5
// speedup vs baseline: 1.6816x; 1.2557x over previous
#include <cuda_runtime.h>

#define B_    16
#define C_    64
#define COUT_ 64
#define L_    16384
#define K_    3
#define CK_   (K_ * C_)   // 192
#define TLC_  128         // l-positions per block
#define XS_   137         // x window stride
#define XWIN_ 137
#define OSTR_ 130         // output staging stride (even -> float2-aligned)
#define NT_   512

// scratch (no allocations allowed)
__device__ float g_wt[CK_ * COUT_];     // [ck][o], ck = k*64 + c

// ---------------- f32x2 helpers ----------------
__device__ __forceinline__ unsigned long long pack2(float lo, float hi) {
    unsigned long long r;
    asm("mov.b64 %0, {%1, %2};" : "=l"(r) : "f"(lo), "f"(hi));
    return r;
}
__device__ __forceinline__ void unpack2(unsigned long long v, float& lo, float& hi) {
    asm("mov.b64 {%0, %1}, %2;" : "=f"(lo), "=f"(hi) : "l"(v));
}
__device__ __forceinline__ void fma2(unsigned long long& d, unsigned long long a,
                                     unsigned long long b) {
    asm("fma.rn.f32x2 %0, %1, %2, %0;" : "+l"(d) : "l"(a), "l"(b));
}

// ================= kernel A: weight transpose =================
__global__ void wt_kernel(const float* __restrict__ weight) {
    int i = blockIdx.x * blockDim.x + threadIdx.x;
    if (i < CK_ * COUT_) {
        int o  = i & 63;
        int ck = i >> 6;
        int c  = ck & 63;
        int k  = ck >> 6;
        g_wt[i] = weight[o * CK_ + c * K_ + k];
    }
}

// ================= fused kernel (512 threads) =================
// dynamic smem (floats), total 45632 (182528 B):
//   x_s  [0, 8768)      | w_s [8768, 21056) | dwA/dwB [21056, 37696) | xv_s [21056, 45632)
//   out_s reuses [0, 8320) after phase B
__global__ __launch_bounds__(NT_, 1) void fused_kernel(
    const float* __restrict__ x,
    const float* __restrict__ wodw, const float* __restrict__ bodw,
    const float* __restrict__ wopw, const float* __restrict__ bopw,
    const float* __restrict__ wmdw, const float* __restrict__ bmdw,
    const float* __restrict__ wmpw, const float* __restrict__ bmpw,
    const float* __restrict__ bias,
    float* __restrict__ out)
{
    extern __shared__ float smem[];
    float* x_s  = smem;
    float* w_s  = smem + 8768;
    float* dwA  = smem + 21056;
    float* dwB  = smem + 29376;
    float* xv_s = smem + 21056;

    __shared__ float s_wdwA[448], s_wdwB[448];
    __shared__ float s_bdwA[64],  s_bdwB[64];
    __shared__ float s_wpwA[192], s_wpwB[192];
    __shared__ float s_bpwA[4],   s_bpwB[4];
    __shared__ float off_s[384], msk_s[384], bias_s[64];

    const int tid = threadIdx.x;
    const int b   = blockIdx.y;
    const int l0  = blockIdx.x * TLC_;

    // ---- stage 0: params + weights + x window ----
    if (tid < 448) { s_wdwA[tid] = wodw[tid]; s_wdwB[tid] = wmdw[tid]; }
    if (tid < 64)  { s_bdwA[tid] = bodw[tid]; s_bdwB[tid] = bmdw[tid]; bias_s[tid] = bias[tid]; }
    if (tid < 192) { s_wpwA[tid] = wopw[tid]; s_wpwB[tid] = wmpw[tid]; }
    if (tid < 3)   { s_bpwA[tid] = bopw[tid]; s_bpwB[tid] = bmpw[tid]; }

    {   // transposed conv weights (coalesced float4)
        const float4* src = (const float4*)g_wt;
        float4* dst = (float4*)w_s;
        #pragma unroll
        for (int i = 0; i < 6; ++i) dst[i * NT_ + tid] = src[i * NT_ + tid];
    }
    // x window: x_s[c*137 + lw] = x[b, c, l0-3+lw]
    #pragma unroll 4
    for (int i = tid; i < 64 * XS_; i += NT_) {
        int c  = i / XS_;
        int lw = i - c * XS_;
        int idx = l0 - 3 + lw;
        x_s[i] = (idx >= 0 && idx < L_) ? x[(long)(b * 64 + c) * L_ + idx] : 0.f;
    }
    __syncthreads();

    // ---- stage 1: depthwise 7-tap conv, both branches ----
    #pragma unroll
    for (int it = 0; it < 16; ++it) {
        int item = it * NT_ + tid;
        int li = item & 127;
        int c  = item >> 7;
        const float* xr = x_s + c * XS_;
        float sA = s_bdwA[c], sB = s_bdwB[c];
        #pragma unroll
        for (int t = 0; t < 7; ++t) {
            float xv = xr[li + t];
            sA = fmaf(xv, s_wdwA[c * 7 + t], sA);
            sB = fmaf(xv, s_wdwB[c * 7 + t], sB);
        }
        dwA[li * 65 + c] = sA;
        dwB[li * 65 + c] = sB;
    }
    __syncthreads();

    // ---- stage 2: 1x1 conv -> offset / mask (sigmoid) ----
    if (tid < 384) {
        int li = tid / 3;
        int k  = tid - li * 3;
        float oA = s_bpwA[k], oB = s_bpwB[k];
        #pragma unroll 8
        for (int c = 0; c < 64; ++c) {
            oA = fmaf(dwA[li * 65 + c], s_wpwA[k * 64 + c], oA);
            oB = fmaf(dwB[li * 65 + c], s_wpwB[k * 64 + c], oB);
        }
        off_s[tid] = oA;
        msk_s[tid] = 1.f / (1.f + __expf(-oB));
    }
    __syncthreads();

    // ---- stage 3: deformable gather + interp -> xv_s[ck][li] ----
    #pragma unroll 4
    for (int it = 0; it < 48; ++it) {
        int idx = it * NT_ + tid;
        int li = idx & 127;
        int ck = idx >> 7;
        int c  = ck & 63;
        int k  = ck >> 6;
        float off = off_s[li * 3 + k];
        float m   = msk_s[li * 3 + k];
        float p  = (float)(l0 + li - 1 + k) + off;
        float fi = floorf(p);
        float f  = p - fi;
        int i0 = (int)fi;
        int i1 = i0 + 1;
        int lw0 = i0 - (l0 - 3);
        int lw1 = lw0 + 1;
        const float* xr = x + (long)(b * 64 + c) * L_;
        float x0, x1;
        if (lw0 >= 0 && lw0 < XWIN_) x0 = x_s[c * XS_ + lw0];
        else x0 = (i0 >= 0 && i0 < L_) ? xr[i0] : 0.f;
        if (lw1 >= 0 && lw1 < XWIN_) x1 = x_s[c * XS_ + lw1];
        else x1 = (i1 >= 0 && i1 < L_) ? xr[i1] : 0.f;
        xv_s[ck * 128 + li] = ((1.f - f) * x0 + f * x1) * m;
    }
    __syncthreads();

    // ---- stage 4: out[o][l] = sum_ck w[ck][o] * xv[ck][l] ----
    // 4 o x 4 l per thread, f32x2 over native l-pairs
    const int og = tid & 15;
    const int lg = tid >> 4;           // 0..31
    const int obase = og * 4;
    const int lbase = lg * 4;

    unsigned long long acc[8];         // [oo*2 + lp]
    #pragma unroll
    for (int i = 0; i < 8; ++i) acc[i] = 0ULL;

    const float* wp = w_s + obase;
    const float* xp = xv_s + lbase;

    #pragma unroll 4
    for (int ck = 0; ck < CK_; ++ck) {
        float4 wv = *(const float4*)wp;            wp += 64;
        ulonglong2 xv2 = *(const ulonglong2*)xp;   xp += 128;
        unsigned long long x01 = xv2.x;
        unsigned long long x23 = xv2.y;
        unsigned long long w0 = pack2(wv.x, wv.x);
        unsigned long long w1 = pack2(wv.y, wv.y);
        unsigned long long w2 = pack2(wv.z, wv.z);
        unsigned long long w3 = pack2(wv.w, wv.w);
        fma2(acc[0], w0, x01); fma2(acc[1], w0, x23);
        fma2(acc[2], w1, x01); fma2(acc[3], w1, x23);
        fma2(acc[4], w2, x01); fma2(acc[5], w2, x23);
        fma2(acc[6], w3, x01); fma2(acc[7], w3, x23);
    }
    __syncthreads();

    // ---- stage 5: stage + coalesced store ----
    float* out_s = smem;   // [o][l] stride OSTR_ (even -> aligned)
    #pragma unroll
    for (int oo = 0; oo < 4; ++oo) {
        #pragma unroll
        for (int lp = 0; lp < 2; ++lp) {
            float lo, hi;
            unpack2(acc[oo * 2 + lp], lo, hi);
            *(float2*)&out_s[(obase + oo) * OSTR_ + lbase + lp * 2] =
                make_float2(lo, hi);
        }
    }
    __syncthreads();

    #pragma unroll
    for (int it = 0; it < 16; ++it) {
        int i = it * NT_ + tid;
        int o = i >> 7;
        int l = i & 127;
        out[((long)(b * 64 + o)) * L_ + l0 + l] = out_s[o * OSTR_ + l] + bias_s[o];
    }
}

// ================= host =================
extern "C" void kernel_launch(void* const* d_in, const int* in_sizes, int n_in,
                              void* d_out, int out_size) {
    const float* x      = (const float*)d_in[0];
    const float* wodw   = (const float*)d_in[1];
    const float* bodw   = (const float*)d_in[2];
    const float* wopw   = (const float*)d_in[3];
    const float* bopw   = (const float*)d_in[4];
    const float* wmdw   = (const float*)d_in[5];
    const float* bmdw   = (const float*)d_in[6];
    const float* wmpw   = (const float*)d_in[7];
    const float* bmpw   = (const float*)d_in[8];
    const float* weight = (const float*)d_in[9];
    const float* bias   = (const float*)d_in[10];
    float* out = (float*)d_out;

    wt_kernel<<<(CK_ * COUT_ + 255) / 256, 256>>>(weight);

    const int smem_f = 45632 * (int)sizeof(float);  // 182528 B
    cudaFuncSetAttribute(fused_kernel, cudaFuncAttributeMaxDynamicSharedMemorySize, smem_f);
    dim3 grid(L_ / TLC_, B_);
    fused_kernel<<<grid, NT_, smem_f>>>(x, wodw, bodw, wopw, bopw,
                                        wmdw, bmdw, wmpw, bmpw, bias, out);
}

// round 6
// speedup vs baseline: 1.7087x; 1.0161x over previous
#include <cuda_runtime.h>

#define B_    16
#define C_    64
#define COUT_ 64
#define L_    16384
#define K_    3
#define CK_   (K_ * C_)   // 192
#define TL_   64          // l-positions per block
#define OSTR_ 66          // output staging stride (even)
#define NT_   256

// scratch (no allocations allowed)
__device__ float g_wt[CK_ * COUT_];     // [ck][o], ck = k*64 + c

// ---------------- f32x2 helpers ----------------
__device__ __forceinline__ unsigned long long pack2(float lo, float hi) {
    unsigned long long r;
    asm("mov.b64 %0, {%1, %2};" : "=l"(r) : "f"(lo), "f"(hi));
    return r;
}
__device__ __forceinline__ void unpack2(unsigned long long v, float& lo, float& hi) {
    asm("mov.b64 {%0, %1}, %2;" : "=f"(lo), "=f"(hi) : "l"(v));
}
__device__ __forceinline__ void fma2(unsigned long long& d, unsigned long long a,
                                     unsigned long long b) {
    asm("fma.rn.f32x2 %0, %1, %2, %0;" : "+l"(d) : "l"(a), "l"(b));
}

// ================= kernel A: weight transpose =================
__global__ void wt_kernel(const float* __restrict__ weight) {
    int i = blockIdx.x * blockDim.x + threadIdx.x;
    if (i < CK_ * COUT_) {
        int o  = i & 63;
        int ck = i >> 6;
        int c  = ck & 63;
        int k  = ck >> 6;
        g_wt[i] = weight[o * CK_ + c * K_ + k];
    }
}

// ================= fused kernel: 256 thr, 2 blocks/SM =================
// dynamic smem (floats), 24576 total (98304 B):
//   xv_s [0, 12288)      [ck][li]  (out_s reuses [0,4224) at the end)
//   dwA  [12288, 16448)  [li][c] stride 65   } dead after stage 2;
//   dwB  [16448, 20608)                      } w_s [12288,24576) loaded after
__global__ __launch_bounds__(NT_, 2) void fused_kernel(
    const float* __restrict__ x,
    const float* __restrict__ wodw, const float* __restrict__ bodw,
    const float* __restrict__ wopw, const float* __restrict__ bopw,
    const float* __restrict__ wmdw, const float* __restrict__ bmdw,
    const float* __restrict__ wmpw, const float* __restrict__ bmpw,
    const float* __restrict__ bias,
    float* __restrict__ out)
{
    extern __shared__ float smem[];
    float* xv_s = smem;           // 12288 floats
    float* dwA  = smem + 12288;   // 4160
    float* dwB  = smem + 16448;   // 4160
    float* w_s  = smem + 12288;   // 12288 (after stage 2)

    __shared__ float s_wdwA[448], s_wdwB[448];
    __shared__ float s_bdwA[64],  s_bdwB[64];
    __shared__ float s_wpwA[192], s_wpwB[192];
    __shared__ float s_bpwA[4],   s_bpwB[4];
    __shared__ float off_s[192], msk_s[192], bias_s[64];

    const int tid = threadIdx.x;
    const int b   = blockIdx.y;
    const int l0  = blockIdx.x * TL_;
    const float* xb = x + (long)b * 64 * L_;

    // ---- stage 0: small params ----
    if (tid < 192) {
        s_wdwA[tid] = wodw[tid];       s_wdwB[tid] = wmdw[tid];
        s_wdwA[tid + 256] = wodw[tid + 256];
        s_wdwB[tid + 256] = wmdw[tid + 256];
        s_wpwA[tid] = wopw[tid];       s_wpwB[tid] = wmpw[tid];
    } else {
        int t = tid - 192;   // 0..63
        s_wdwA[192 + t] = wodw[192 + t];  s_wdwB[192 + t] = wmdw[192 + t];
        s_bdwA[t] = bodw[t];  s_bdwB[t] = bmdw[t];  bias_s[t] = bias[t];
        if (t < 3) { s_bpwA[t] = bopw[t]; s_bpwB[t] = bmpw[t]; }
    }
    __syncthreads();

    // ---- stage 1: depthwise 7-tap conv (direct global reads) ----
    {
        const int li = tid & 63;
        const int c0 = tid >> 6;      // 0..3
        #pragma unroll
        for (int it = 0; it < 16; ++it) {
            int c = it * 4 + c0;
            const float* xr = xb + c * L_;
            float sA = s_bdwA[c], sB = s_bdwB[c];
            #pragma unroll
            for (int t = 0; t < 7; ++t) {
                int idx = l0 + li - 3 + t;
                float xv = (idx >= 0 && idx < L_) ? __ldg(xr + idx) : 0.f;
                sA = fmaf(xv, s_wdwA[c * 7 + t], sA);
                sB = fmaf(xv, s_wdwB[c * 7 + t], sB);
            }
            dwA[li * 65 + c] = sA;
            dwB[li * 65 + c] = sB;
        }
    }
    __syncthreads();

    // ---- stage 2: 1x1 conv -> offset / mask (sigmoid) ----
    if (tid < 192) {
        int li = tid / 3;
        int k  = tid - li * 3;
        float oA = s_bpwA[k], oB = s_bpwB[k];
        #pragma unroll 8
        for (int c = 0; c < 64; ++c) {
            oA = fmaf(dwA[li * 65 + c], s_wpwA[k * 64 + c], oA);
            oB = fmaf(dwB[li * 65 + c], s_wpwB[k * 64 + c], oB);
        }
        off_s[tid] = oA;
        msk_s[tid] = 1.f / (1.f + __expf(-oB));
    }
    __syncthreads();

    // ---- stage 3: load conv weights + deformable gather ----
    {   // w_s[ck][o] (overwrites dw region)
        const float4* src = (const float4*)g_wt;
        float4* dst = (float4*)w_s;
        #pragma unroll
        for (int i = 0; i < 12; ++i) dst[i * NT_ + tid] = src[i * NT_ + tid];
    }
    {
        const int li  = tid & 63;
        const int ck0 = tid >> 6;     // 0..3
        #pragma unroll 4
        for (int it = 0; it < 48; ++it) {
            int ck = it * 4 + ck0;
            int c  = ck & 63;
            int k  = ck >> 6;
            float off = off_s[li * 3 + k];
            float m   = msk_s[li * 3 + k];
            float p  = (float)(l0 + li - 1 + k) + off;
            float fi = floorf(p);
            float f  = p - fi;
            int i0 = (int)fi;
            int i1 = i0 + 1;
            const float* xr = xb + c * L_;
            float x0 = (i0 >= 0 && i0 < L_) ? __ldg(xr + i0) : 0.f;
            float x1 = (i1 >= 0 && i1 < L_) ? __ldg(xr + i1) : 0.f;
            xv_s[ck * 64 + li] = ((1.f - f) * x0 + f * x1) * m;
        }
    }
    __syncthreads();

    // ---- stage 4: out[o][l] = sum_ck w[ck][o] * xv[ck][l] ----
    // thread owns 2 o x 8 l; w pair from one native LDS.64, x as 2 LDS.128
    const int obase = (tid & 31) * 2;
    const int lbase = (tid >> 5) * 8;

    unsigned long long acc[8];        // [oo*4 + lp]
    #pragma unroll
    for (int i = 0; i < 8; ++i) acc[i] = 0ULL;

    const float* wp = w_s + obase;
    const float* xp = xv_s + lbase;

    #pragma unroll 4
    for (int ck = 0; ck < CK_; ++ck) {
        float2 wv = *(const float2*)wp;            wp += 64;
        ulonglong2 xv2 = *(const ulonglong2*)xp;
        ulonglong2 xv3 = *(const ulonglong2*)(xp + 4);
        xp += 64;
        unsigned long long w0 = pack2(wv.x, wv.x);
        unsigned long long w1 = pack2(wv.y, wv.y);
        fma2(acc[0], w0, xv2.x); fma2(acc[1], w0, xv2.y);
        fma2(acc[2], w0, xv3.x); fma2(acc[3], w0, xv3.y);
        fma2(acc[4], w1, xv2.x); fma2(acc[5], w1, xv2.y);
        fma2(acc[6], w1, xv3.x); fma2(acc[7], w1, xv3.y);
    }
    __syncthreads();

    // ---- stage 5: stage + coalesced store (reuse xv region) ----
    float* out_s = smem;   // [o][l] stride OSTR_ (even -> float2 aligned)
    #pragma unroll
    for (int oo = 0; oo < 2; ++oo) {
        #pragma unroll
        for (int lp = 0; lp < 4; ++lp) {
            float lo, hi;
            unpack2(acc[oo * 4 + lp], lo, hi);
            *(float2*)&out_s[(obase + oo) * OSTR_ + lbase + lp * 2] =
                make_float2(lo, hi);
        }
    }
    __syncthreads();

    {
        const int l = tid & 63;
        const int o0 = tid >> 6;
        #pragma unroll
        for (int it = 0; it < 16; ++it) {
            int o = it * 4 + o0;
            out[((long)(b * 64 + o)) * L_ + l0 + l] = out_s[o * OSTR_ + l] + bias_s[o];
        }
    }
}

// ================= host =================
extern "C" void kernel_launch(void* const* d_in, const int* in_sizes, int n_in,
                              void* d_out, int out_size) {
    const float* x      = (const float*)d_in[0];
    const float* wodw   = (const float*)d_in[1];
    const float* bodw   = (const float*)d_in[2];
    const float* wopw   = (const float*)d_in[3];
    const float* bopw   = (const float*)d_in[4];
    const float* wmdw   = (const float*)d_in[5];
    const float* bmdw   = (const float*)d_in[6];
    const float* wmpw   = (const float*)d_in[7];
    const float* bmpw   = (const float*)d_in[8];
    const float* weight = (const float*)d_in[9];
    const float* bias   = (const float*)d_in[10];
    float* out = (float*)d_out;

    wt_kernel<<<(CK_ * COUT_ + 255) / 256, 256>>>(weight);

    const int smem_f = 24576 * (int)sizeof(float);  // 98304 B
    cudaFuncSetAttribute(fused_kernel, cudaFuncAttributeMaxDynamicSharedMemorySize, smem_f);
    dim3 grid(L_ / TL_, B_);
    fused_kernel<<<grid, NT_, smem_f>>>(x, wodw, bodw, wopw, bopw,
                                        wmdw, bmdw, wmpw, bmpw, bias, out);
}